// round 8
// baseline (speedup 1.0000x reference)
#include <cuda_runtime.h>

// Fixed problem shape
#define NPIX      102400            // B*H*W = 4*160*160
#define HW        25600             // H*W
#define NV        1024
#define OUT_ELEMS (NV * 2 * 32 * 32)   // 524,288 float4

// Gaussian in bin coordinates: t = (x+1)*16 - 0.5, sigma_bins = 0.8
// log2-space coefficient: c = -0.5/(0.8^2) * log2(e)
#define CEXP   (-1.12710546f)
#define SKIPTH (2e-5f)
// g_j = exp(-0.78125 * j^2) for the within-chunk quadratic chain
#define G1 (0.45783335f)
#define G2 (0.043936934f)
#define G3 (8.8382833e-4f)

__device__ int g_sizes[NV];

// ---------------------------------------------------------------------------
// Kernel 1: zero output + g_sizes (1024 x 256 x 2 float4 = OUT_ELEMS exactly)
// ---------------------------------------------------------------------------
__global__ void zero_kernel(float4* __restrict__ out) {
    int t4 = blockIdx.x * 512 + threadIdx.x;
    float4 z = make_float4(0.f, 0.f, 0.f, 0.f);
    out[t4]       = z;
    out[t4 + 256] = z;
    int i = blockIdx.x * blockDim.x + threadIdx.x;
    if (i < NV) g_sizes[i] = 0;
}

// ---------------------------------------------------------------------------
// Kernel 2: segment bincount (ordered after zero_kernel)
// ---------------------------------------------------------------------------
__global__ void count_kernel(const int* __restrict__ seg) {
    int n = blockIdx.x * blockDim.x + threadIdx.x;
    if (n < NPIX) atomicAdd(&g_sizes[seg[n]], 1);
}

// ---------------------------------------------------------------------------
// Predicated vector reduction: issue red.v4 only if gate > SKIPTH.
// ---------------------------------------------------------------------------
__device__ __forceinline__ void red4p(float gate, float* p,
                                      float a, float b, float c, float d) {
    asm volatile(
        "{\n\t"
        ".reg .pred pg;\n\t"
        "setp.gt.f32 pg, %0, %1;\n\t"
        "@pg red.global.add.v4.f32 [%2], {%3,%4,%5,%6};\n\t"
        "}"
        :: "f"(gate), "f"(SKIPTH), "l"(p), "f"(a), "f"(b), "f"(c), "f"(d)
        : "memory");
}

// ---------------------------------------------------------------------------
// One pair update: warp covers the whole 6x12 window.
// Lane l<18 owns (row = lo + l/3, chunk col = (l%3)*4).
// All 18 active lanes issue ONE red4 -> addresses span only 6 x 128B lines
// (row stride = 32 floats = 128B; base is 8KB aligned).
// q-weights via quadratic chain: w_j = w0 * r^j * g_j (2 exps instead of 4).
// ---------------------------------------------------------------------------
__device__ __forceinline__ void pair_update(float* base, float tp, float tq,
                                            float inv, int m, int c4, bool act) {
    int lo = min(26, max(0, __float2int_rd(tp) - 2));
    int qa = min(20, max(0, (__float2int_rd(tq) - 3) & ~3));

    float up = tp - (float)(lo + m);
    float wp = exp2f(CEXP * up * up);          // this lane's row weight

    float uq = tq - (float)(qa + c4);
    float w0 = exp2f(CEXP * uq * uq);          // chunk-base weight
    float r  = exp2f(-2.0f * CEXP * uq);       // ratio term
    float r2 = r * r;
    float q0 = w0;
    float q1 = w0 * r  * G1;
    float q2 = w0 * r2 * G2;
    float q3 = w0 * r2 * r * G3;

    float gate = act ? wp * fmaxf(fmaxf(q0, q1), fmaxf(q2, q3)) : -1.0f;
    float a = wp * inv;
    float* addr = base + (lo + m) * 32 + qa + c4;
    red4p(gate, addr, a * q0, a * q1, a * q2, a * q3);
}

// ---------------------------------------------------------------------------
// Kernel 3: warp-per-pixel windowed Parzen scatter.
// 400 blocks x 256 threads = 3200 warps, each handles 32 pixels.
// ---------------------------------------------------------------------------
__global__ void __launch_bounds__(256)
hist_kernel(const int* __restrict__ seg,
            const int* __restrict__ byx,
            const float* __restrict__ grad,
            float* __restrict__ out) {
    int warp = (blockIdx.x * 256 + threadIdx.x) >> 5;   // 0..3199
    int lane = threadIdx.x & 31;
    int m    = lane / 3;                                // row offset 0..5 (active lanes)
    int c4   = (lane - m * 3) * 4;                      // chunk col 0/4/8
    bool act = lane < 18;
    int n0   = warp * 32;

#pragma unroll 2
    for (int i = 0; i < 32; i++) {
        int n = n0 + i;
        int v = __ldg(&seg[n]);
        float inv = 1.0f / (float)__ldg(&g_sizes[v]);   // den = sizes*(P/32)^2 = sizes

        float t0 = (float)__ldg(&byx[NPIX + n])     * 0.2f - 0.5f;
        float t1 = (float)__ldg(&byx[2 * NPIX + n]) * 0.2f - 0.5f;
        int b  = n / HW;
        int hw = n - b * HW;
        float t2 = __ldg(&grad[b * 2 * HW + hw])      * 16.f + 15.5f;
        float t3 = __ldg(&grad[b * 2 * HW + HW + hw]) * 16.f + 15.5f;

        float* base = out + (size_t)v * 2048;

        pair_update(base, t0, t1, inv, m, c4, act);

        // pair 1: uniform warp-level skip (all lanes same pixel data)
        if (t2 > -3.5f && t2 < 34.5f && t3 > -3.5f && t3 < 34.5f)
            pair_update(base + 1024, t2, t3, inv, m, c4, act);
    }
}

// ---------------------------------------------------------------------------
extern "C" void kernel_launch(void* const* d_in, const int* in_sizes, int n_in,
                              void* d_out, int out_size) {
    const int*   seg  = (const int*)d_in[0];
    const int*   byx  = (const int*)d_in[1];
    const float* grad = (const float*)d_in[2];
    float*       out  = (float*)d_out;

    zero_kernel<<<1024, 256>>>((float4*)out);
    count_kernel<<<(NPIX + 255) / 256, 256>>>(seg);
    hist_kernel<<<400, 256>>>(seg, byx, grad, out);
}